// round 15
// baseline (speedup 1.0000x reference)
#include <cuda_runtime.h>
#include <cuda_fp16.h>
#include <cstdint>
#include <math.h>

// ---------------------------------------------------------------------------
// Problem constants
// ---------------------------------------------------------------------------
#define BB   8
#define LL   1024
#define BL   (BB*LL)
#define QUES 4000
#define EMB  256
#define DM   1024
#define DI   2048
#define NN   16
#define DTR  64

// ---------------------------------------------------------------------------
// Scratch (static device allocations)
// ---------------------------------------------------------------------------
__device__ float  g_dbl  [BL*96];

__device__ __half h_item [BL*DM];
__device__ __half h_inw  [2*DI*DM];
__device__ __half h_ur   [(size_t)BL*2*DI];
__device__ __half h_ucv  [(size_t)BL*DI];
__device__ __half h_xpw  [96*DI];
__device__ __half h_dbl  [BL*96];
__device__ __half h_dtw  [DI*DTR];
__device__ __half h_delta[(size_t)BL*DI];
__device__ __half h_yg   [(size_t)BL*DI];
__device__ __half h_outw [DM*DI];
__device__ __half h_hout [BL*DM];
__device__ __half h_lnout[BL*DM];
__device__ __half h_fcw  [QUES*DM];

// ---------------------------------------------------------------------------
// PTX helpers (arch-generic, sm_80-era)
// ---------------------------------------------------------------------------
__device__ __forceinline__ uint32_t smem_u32(const void* p) {
    uint32_t a;
    asm("{ .reg .u64 t; cvta.to.shared.u64 t, %1; cvt.u32.u64 %0, t; }" : "=r"(a) : "l"(p));
    return a;
}
__device__ __forceinline__ void cp_async16(uint32_t dst, const void* src, int src_bytes) {
    asm volatile("cp.async.cg.shared.global [%0], [%1], 16, %2;"
                 :: "r"(dst), "l"(src), "r"(src_bytes) : "memory");
}
__device__ __forceinline__ void cp_async16u(uint32_t dst, const void* src) {
    asm volatile("cp.async.cg.shared.global [%0], [%1], 16;"
                 :: "r"(dst), "l"(src) : "memory");
}
#define CP_COMMIT()  asm volatile("cp.async.commit_group;" ::: "memory")
#define CP_WAIT(n)   asm volatile("cp.async.wait_group %0;" :: "n"(n) : "memory")

__device__ __forceinline__ void ldsm_x4(uint32_t& r0, uint32_t& r1, uint32_t& r2, uint32_t& r3,
                                        uint32_t addr) {
    asm volatile("ldmatrix.sync.aligned.m8n8.x4.shared.b16 {%0,%1,%2,%3}, [%4];"
                 : "=r"(r0), "=r"(r1), "=r"(r2), "=r"(r3) : "r"(addr));
}
__device__ __forceinline__ void mma_f16(float& c0, float& c1, float& c2, float& c3,
                                        uint32_t a0, uint32_t a1, uint32_t a2, uint32_t a3,
                                        uint32_t b0, uint32_t b1) {
    asm volatile(
        "mma.sync.aligned.m16n8k16.row.col.f32.f16.f16.f32 "
        "{%0,%1,%2,%3}, {%4,%5,%6,%7}, {%8,%9}, {%0,%1,%2,%3};"
        : "+f"(c0), "+f"(c1), "+f"(c2), "+f"(c3)
        : "r"(a0), "r"(a1), "r"(a2), "r"(a3), "r"(b0), "r"(b1));
}

// ---------------------------------------------------------------------------
// fp16 GEMM: C[M,N](OutT) = A[M,K](half,lda) * B[N,K](half,ldb)^T
// CTA 128x128, BK=32, 8 warps (64x32 warp tiles), 5-stage cp.async.
// NB=true: N%128==0 guaranteed (no B bounds checks in load or store).
// EPI: 0 none, 1 bias+softplus(fast), 2 bias+sigmoid(fast)
// ---------------------------------------------------------------------------
#define ROWB   80
#define ATILE_B (128*ROWB)
#define STAGE_B (2*ATILE_B)
#define NSTAGES 5
#define GSMEM   (NSTAGES*STAGE_B)       // 102400 B

template<int EPI, bool SPLITK, bool NB, typename OutT>
__global__ __launch_bounds__(256, 2)
void gemm_h(const __half* __restrict__ A, int lda,
            const __half* __restrict__ B, int ldb,
            OutT* __restrict__ C, int ldc,
            int M, int N, int K, const float* __restrict__ bias)
{
    extern __shared__ char sm[];
    const uint32_t sbase = smem_u32(sm);
    const int tid  = threadIdx.x;
    const int lane = tid & 31;
    const int wid  = tid >> 5;

    const int m0 = blockIdx.y * 128;
    const int n0 = blockIdx.x * 128;
    const int kbase = SPLITK ? blockIdx.z * K : 0;
    const int warp_m = (wid >> 2) * 64;
    const int warp_n = (wid & 3) * 32;

    float acc[4][4][4];
    #pragma unroll
    for (int mi = 0; mi < 4; mi++)
        #pragma unroll
        for (int ni = 0; ni < 4; ni++)
            #pragma unroll
            for (int r = 0; r < 4; r++) acc[mi][ni][r] = 0.f;

    const int NC = K >> 5;

    auto load_stage = [&](int ch, int st) {
        const int k0 = kbase + (ch << 5);
        uint32_t aB = sbase + (uint32_t)st * STAGE_B;
        uint32_t bB = aB + ATILE_B;
        #pragma unroll
        for (int it = 0; it < 2; it++) {
            int idx = tid + it * 256;
            int row = idx >> 2, c = idx & 3;
            cp_async16u(aB + row * ROWB + c * 16,
                        A + (size_t)(m0 + row) * lda + k0 + c * 8);
        }
        #pragma unroll
        for (int it = 0; it < 2; it++) {
            int idx = tid + it * 256;
            int row = idx >> 2, c = idx & 3;
            int gn = n0 + row;
            if constexpr (NB) {
                cp_async16u(bB + row * ROWB + c * 16,
                            B + (size_t)gn * ldb + k0 + c * 8);
            } else {
                int ok = (gn < N) ? 16 : 0;
                const __half* src = B + (size_t)(ok ? gn : 0) * ldb + k0 + c * 8;
                cp_async16(bB + row * ROWB + c * 16, src, ok);
            }
        }
    };

    #pragma unroll
    for (int s = 0; s < 4; s++)
        if (s < NC) { load_stage(s, s); CP_COMMIT(); }

    const uint32_t aOff = (uint32_t)((warp_m + (lane & 15)) * ROWB + ((lane >> 4) << 3) * 2);
    const uint32_t bOff = (uint32_t)(ATILE_B
                        + (warp_n + (lane & 7) + ((lane >> 4) << 3)) * ROWB
                        + (((lane >> 3) & 1) << 3) * 2);

    int stage = 0;
    for (int ch = 0; ch < NC; ch++) {
        const int rem = NC - ch - 1;
        if (rem >= 3)      CP_WAIT(3);
        else if (rem == 2) CP_WAIT(2);
        else if (rem == 1) CP_WAIT(1);
        else               CP_WAIT(0);
        __syncthreads();
        if (ch + 4 < NC) {
            int st = stage + 4; if (st >= NSTAGES) st -= NSTAGES;
            load_stage(ch + 4, st);
            CP_COMMIT();
        }

        const uint32_t stg = sbase + (uint32_t)stage * STAGE_B;
        stage++; if (stage == NSTAGES) stage = 0;

        uint32_t a[2][4][4], b[2][2][4];
        #pragma unroll
        for (int ks = 0; ks < 2; ks++) {
            const uint32_t kb = (uint32_t)(ks * 32);
            #pragma unroll
            for (int mi = 0; mi < 4; mi++)
                ldsm_x4(a[ks][mi][0], a[ks][mi][1], a[ks][mi][2], a[ks][mi][3],
                        stg + aOff + (uint32_t)(mi * 16 * ROWB) + kb);
            #pragma unroll
            for (int p = 0; p < 2; p++)
                ldsm_x4(b[ks][p][0], b[ks][p][1], b[ks][p][2], b[ks][p][3],
                        stg + bOff + (uint32_t)(p * 16 * ROWB) + kb);
        }
        #pragma unroll
        for (int ks = 0; ks < 2; ks++)
            #pragma unroll
            for (int mi = 0; mi < 4; mi++)
                #pragma unroll
                for (int ni = 0; ni < 4; ni++) {
                    const int p = ni >> 1, sel = (ni & 1) * 2;
                    mma_f16(acc[mi][ni][0], acc[mi][ni][1], acc[mi][ni][2], acc[mi][ni][3],
                            a[ks][mi][0], a[ks][mi][1], a[ks][mi][2], a[ks][mi][3],
                            b[ks][p][sel], b[ks][p][sel + 1]);
                }
    }

    const int g  = lane >> 2;
    const int tg = lane & 3;
    #pragma unroll
    for (int mi = 0; mi < 4; mi++) {
        #pragma unroll
        for (int ni = 0; ni < 4; ni++) {
            int row = m0 + warp_m + mi * 16 + g;
            int col = n0 + warp_n + ni * 8 + 2 * tg;
            float v[4] = {acc[mi][ni][0], acc[mi][ni][1], acc[mi][ni][2], acc[mi][ni][3]};
            if constexpr (SPLITK) {
                float* Cf = (float*)C;
                if (col < N) {
                    atomicAdd(Cf + (size_t)row * ldc + col,       v[0]);
                    atomicAdd(Cf + (size_t)(row + 8) * ldc + col, v[2]);
                }
                if (col + 1 < N) {
                    atomicAdd(Cf + (size_t)row * ldc + col + 1,       v[1]);
                    atomicAdd(Cf + (size_t)(row + 8) * ldc + col + 1, v[3]);
                }
                continue;
            }
            if (EPI != 0) {
                #pragma unroll
                for (int j = 0; j < 4; j++) {
                    int cc = col + (j & 1);
                    if (NB || cc < N) {
                        float t = v[j] + bias[cc];
                        if (EPI == 1) v[j] = (t > 20.f) ? t : __logf(1.f + __expf(t));
                        else          v[j] = __fdividef(1.f, 1.f + __expf(-t));
                    }
                }
            }
            if (NB || col + 1 < N) {
                if constexpr (sizeof(OutT) == 2) {
                    *(__half2*)((__half*)C + (size_t)row * ldc + col)
                        = __floats2half2_rn(v[0], v[1]);
                    *(__half2*)((__half*)C + (size_t)(row + 8) * ldc + col)
                        = __floats2half2_rn(v[2], v[3]);
                } else {
                    *(float2*)((float*)C + (size_t)row * ldc + col)       = make_float2(v[0], v[1]);
                    *(float2*)((float*)C + (size_t)(row + 8) * ldc + col) = make_float2(v[2], v[3]);
                }
            } else if (col < N) {
                if constexpr (sizeof(OutT) == 2) {
                    ((__half*)C)[(size_t)row * ldc + col]       = __float2half(v[0]);
                    ((__half*)C)[(size_t)(row + 8) * ldc + col] = __float2half(v[2]);
                } else {
                    ((float*)C)[(size_t)row * ldc + col]       = v[0];
                    ((float*)C)[(size_t)(row + 8) * ldc + col] = v[2];
                }
            }
        }
    }
}

// ---------------------------------------------------------------------------
// Fused weight conversion
// ---------------------------------------------------------------------------
__global__ void f2h_all_kernel(const float* w0, const float* w1, const float* w2,
                               const float* w3, const float* w4,
                               __half* d0, __half* d1, __half* d2,
                               __half* d3, __half* d4)
{
    const int n0 = 2*DI*DM, n1 = 96*DI, n2 = DI*DTR, n3 = DM*DI, n4 = QUES*DM;
    long i = ((long)blockIdx.x * 256 + threadIdx.x) * 4;
    const float* src; __half* dst; long j = i;
    if      (j < n0)         { src = w0; dst = d0; }
    else if ((j -= n0) < n1) { src = w1; dst = d1; }
    else if ((j -= n1) < n2) { src = w2; dst = d2; }
    else if ((j -= n2) < n3) { src = w3; dst = d3; }
    else if ((j -= n3) < n4) { src = w4; dst = d4; }
    else return;
    float4 v = *(const float4*)(src + j);
    __half2* d = (__half2*)(dst + j);
    d[0] = __floats2half2_rn(v.x, v.y);
    d[1] = __floats2half2_rn(v.z, v.w);
}

__global__ void f2h_kernel(const float* __restrict__ src, __half* __restrict__ dst, int n) {
    int i = (blockIdx.x * 256 + threadIdx.x) * 4;
    if (i < n) {
        float4 v = *(const float4*)(src + i);
        __half2* d = (__half2*)(dst + i);
        d[0] = __floats2half2_rn(v.x, v.y);
        d[1] = __floats2half2_rn(v.z, v.w);
    }
}

__global__ void zero_kernel(float* __restrict__ p, int n) {
    int i = blockIdx.x * 1024 + threadIdx.x;
    if (i < n) p[i] = 0.f;
}

// ---------------------------------------------------------------------------
// Embedding gather + concat + LayerNorm0 -> fp16
// ---------------------------------------------------------------------------
__global__ void embed_ln0_kernel(const int* __restrict__ x, const int* __restrict__ qid,
                                 const float* __restrict__ emb, const float* __restrict__ qc,
                                 const float* __restrict__ g, const float* __restrict__ b,
                                 __half* __restrict__ itemh)
{
    int tok = blockIdx.x;
    int t   = threadIdx.x;
    int xv  = x[tok];
    int qv  = qid[tok];

    float v[4];
    v[0] = emb[(size_t)xv*EMB + t];
    v[1] = qc [(size_t)qv*768 + t];
    v[2] = qc [(size_t)qv*768 + 256 + t];
    v[3] = qc [(size_t)qv*768 + 512 + t];

    float s  = v[0]+v[1]+v[2]+v[3];
    float sq = v[0]*v[0]+v[1]*v[1]+v[2]*v[2]+v[3]*v[3];
    #pragma unroll
    for (int o = 16; o > 0; o >>= 1) {
        s  += __shfl_xor_sync(0xffffffffu, s,  o);
        sq += __shfl_xor_sync(0xffffffffu, sq, o);
    }
    __shared__ float ws[8], wq[8];
    int lane = t & 31, warp = t >> 5;
    if (lane == 0) { ws[warp] = s; wq[warp] = sq; }
    __syncthreads();
    __shared__ float s_mean, s_rstd;
    if (t == 0) {
        float ts = 0.f, tq = 0.f;
        #pragma unroll
        for (int i = 0; i < 8; i++) { ts += ws[i]; tq += wq[i]; }
        float mean = ts * (1.0f/DM);
        float var  = tq * (1.0f/DM) - mean*mean;
        s_mean = mean;
        s_rstd = rsqrtf(var + 1e-12f);
    }
    __syncthreads();
    float mean = s_mean, rstd = s_rstd;
    #pragma unroll
    for (int i = 0; i < 4; i++) {
        int j = t + i*256;
        itemh[(size_t)tok*DM + j] = __float2half((v[i] - mean) * rstd * g[j] + b[j]);
    }
}

// ---------------------------------------------------------------------------
// Residual add (fp16 + fp16) + LayerNorm1 -> fp16
// ---------------------------------------------------------------------------
__global__ void add_ln_kernel(const __half* __restrict__ a, const __half* __restrict__ res,
                              const float* __restrict__ g, const float* __restrict__ b,
                              __half* __restrict__ out)
{
    int tok = blockIdx.x;
    int t   = threadIdx.x;
    float v[4];
    #pragma unroll
    for (int i = 0; i < 4; i++) {
        int j = t + i*256;
        v[i] = __half2float(a[(size_t)tok*DM + j]) + __half2float(res[(size_t)tok*DM + j]);
    }
    float s  = v[0]+v[1]+v[2]+v[3];
    float sq = v[0]*v[0]+v[1]*v[1]+v[2]*v[2]+v[3]*v[3];
    #pragma unroll
    for (int o = 16; o > 0; o >>= 1) {
        s  += __shfl_xor_sync(0xffffffffu, s,  o);
        sq += __shfl_xor_sync(0xffffffffu, sq, o);
    }
    __shared__ float ws[8], wq[8];
    int lane = t & 31, warp = t >> 5;
    if (lane == 0) { ws[warp] = s; wq[warp] = sq; }
    __syncthreads();
    __shared__ float s_mean, s_rstd;
    if (t == 0) {
        float ts = 0.f, tq = 0.f;
        #pragma unroll
        for (int i = 0; i < 8; i++) { ts += ws[i]; tq += wq[i]; }
        float mean = ts * (1.0f/DM);
        float var  = tq * (1.0f/DM) - mean*mean;
        s_mean = mean;
        s_rstd = rsqrtf(var + 1e-12f);
    }
    __syncthreads();
    float mean = s_mean, rstd = s_rstd;
    #pragma unroll
    for (int i = 0; i < 4; i++) {
        int j = t + i*256;
        out[(size_t)tok*DM + j] = __float2half((v[i] - mean) * rstd * g[j] + b[j]);
    }
}

// ---------------------------------------------------------------------------
// Depthwise causal conv (K=4) + SiLU — 128-long l-chunks
// ---------------------------------------------------------------------------
#define CONV_CHUNK 128
__global__ void conv_silu_kernel(const __half* __restrict__ ur,
                                 const float* __restrict__ w,
                                 const float* __restrict__ cb,
                                 __half* __restrict__ outh)
{
    int d  = blockIdx.x * 256 + threadIdx.x;
    int l0 = blockIdx.y * CONV_CHUNK;
    int b  = blockIdx.z;
    float w0 = w[d*4+0], w1 = w[d*4+1], w2 = w[d*4+2], w3 = w[d*4+3];
    float bias = cb[d];
    size_t rbase = (size_t)b * LL;

    float x0 = 0.f, x1 = 0.f, x2 = 0.f;
    if (l0 >= 1) x2 = __half2float(ur[(rbase + l0 - 1)*(2*DI) + d]);
    if (l0 >= 2) x1 = __half2float(ur[(rbase + l0 - 2)*(2*DI) + d]);
    if (l0 >= 3) x0 = __half2float(ur[(rbase + l0 - 3)*(2*DI) + d]);

    #pragma unroll 4
    for (int l = l0; l < l0 + CONV_CHUNK; l++) {
        size_t idx = rbase + l;
        float xc = __half2float(ur[idx*(2*DI) + d]);
        float c  = fmaf(x0, w0, fmaf(x1, w1, fmaf(x2, w2, fmaf(xc, w3, bias))));
        float o  = c * __fdividef(1.f, 1.f + __expf(-c));
        outh[idx*DI + d] = __float2half(o);
        x0 = x1; x1 = x2; x2 = xc;
    }
}

// ---------------------------------------------------------------------------
// Selective scan v2: smem-staged, cp.async double-buffered, coalesced.
// ---------------------------------------------------------------------------
#define SCH 32
__global__ __launch_bounds__(256)
void scan_kernel(const __half* __restrict__ delta,
                 const __half* __restrict__ ucv,
                 const float*  __restrict__ dbl,
                 const __half* __restrict__ ur,
                 const float*  __restrict__ A_log,
                 const float*  __restrict__ D_param,
                 __half* __restrict__ yg)
{
    __shared__ __align__(16) __half sdelta[2][SCH][16];
    __shared__ __align__(16) __half sucv  [2][SCH][16];
    __shared__ __align__(16) __half sr    [2][SCH][16];
    __shared__ __align__(16) float  sdbl  [2][SCH][32];
    __shared__ __align__(16) __half sy    [SCH][16];

    const int t  = threadIdx.x;
    const int n  = t & 15;
    const int dd = t >> 4;
    const int d0 = blockIdx.x * 16;
    const int b  = blockIdx.y;
    const int d  = d0 + dd;
    const size_t base = (size_t)b * LL;

    const float A  = -expf(A_log[d*NN + n]);
    const float Dd = D_param[d];
    float h = 0.f;

    auto load_chunk = [&](int c, int buf) {
        const size_t l0 = base + (size_t)c * SCH;
        if (t < 64) {
            int l = t >> 1, p = t & 1;
            cp_async16u(smem_u32(&sdelta[buf][l][p*8]),
                        delta + (l0 + l)*DI + d0 + p*8);
        } else if (t < 128) {
            int tt = t - 64; int l = tt >> 1, p = tt & 1;
            cp_async16u(smem_u32(&sucv[buf][l][p*8]),
                        ucv + (l0 + l)*DI + d0 + p*8);
        } else if (t < 192) {
            int tt = t - 128; int l = tt >> 1, p = tt & 1;
            cp_async16u(smem_u32(&sr[buf][l][p*8]),
                        ur + (l0 + l)*(size_t)(2*DI) + DI + d0 + p*8);
        }
        {
            int l = t >> 3, p = t & 7;
            cp_async16u(smem_u32(&sdbl[buf][l][p*4]),
                        dbl + (l0 + l)*96 + 64 + p*4);
        }
    };

    load_chunk(0, 0);
    CP_COMMIT();

    const int NCH = LL / SCH;
    for (int c = 0; c < NCH; c++) {
        const int buf = c & 1;
        if (c + 1 < NCH) { load_chunk(c + 1, (c + 1) & 1); CP_COMMIT(); CP_WAIT(1); }
        else             { CP_WAIT(0); }
        __syncthreads();

        #pragma unroll 4
        for (int l = 0; l < SCH; l++) {
            float dlt = __half2float(sdelta[buf][l][dd]);
            float uu  = __half2float(sucv  [buf][l][dd]);
            float Bv  = sdbl[buf][l][n];
            float Cv  = sdbl[buf][l][16 + n];
            h = fmaf(__expf(dlt * A), h, dlt * uu * Bv);
            float p = h * Cv;
            p += __shfl_xor_sync(0xffffffffu, p, 8);
            p += __shfl_xor_sync(0xffffffffu, p, 4);
            p += __shfl_xor_sync(0xffffffffu, p, 2);
            p += __shfl_xor_sync(0xffffffffu, p, 1);
            if (n == 0) {
                float r  = __half2float(sr[buf][l][dd]);
                float g_ = r * __fdividef(1.f, 1.f + __expf(-r));
                sy[l][dd] = __float2half((p + uu * Dd) * g_);
            }
        }
        __syncthreads();
        {
            int l = t >> 3, p = t & 7;
            *(__half2*)(yg + (base + (size_t)c * SCH + l)*DI + d0 + p*2)
                = *(__half2*)&sy[l][p*2];
        }
    }
}

// ---------------------------------------------------------------------------
// Launch
// ---------------------------------------------------------------------------
extern "C" void kernel_launch(void* const* d_in, const int* in_sizes, int n_in,
                              void* d_out, int out_size)
{
    const int*   x     = (const int*)  d_in[0];
    const int*   qid   = (const int*)  d_in[1];
    const float* emb   = (const float*)d_in[2];
    const float* qc    = (const float*)d_in[3];
    const float* ln0g  = (const float*)d_in[4];
    const float* ln0b  = (const float*)d_in[5];
    const float* inw   = (const float*)d_in[6];
    const float* convw = (const float*)d_in[7];
    const float* convb = (const float*)d_in[8];
    const float* xpw   = (const float*)d_in[9];
    const float* dtw   = (const float*)d_in[10];
    const float* dtb   = (const float*)d_in[11];
    const float* alog  = (const float*)d_in[12];
    const float* dpar  = (const float*)d_in[13];
    const float* outw  = (const float*)d_in[14];
    const float* ln1g  = (const float*)d_in[15];
    const float* ln1b  = (const float*)d_in[16];
    const float* fcw   = (const float*)d_in[17];
    const float* fcb   = (const float*)d_in[18];
    float* out = (float*)d_out;

    float *dbl;
    cudaGetSymbolAddress((void**)&dbl, g_dbl);

    __half *itemh, *inwh, *urh, *ucvh, *xpwh, *dblh, *dtwh, *deltah, *ygh, *outwh, *houth, *lnouth, *fcwh;
    cudaGetSymbolAddress((void**)&itemh,  h_item);
    cudaGetSymbolAddress((void**)&inwh,   h_inw);
    cudaGetSymbolAddress((void**)&urh,    h_ur);
    cudaGetSymbolAddress((void**)&ucvh,   h_ucv);
    cudaGetSymbolAddress((void**)&xpwh,   h_xpw);
    cudaGetSymbolAddress((void**)&dblh,   h_dbl);
    cudaGetSymbolAddress((void**)&dtwh,   h_dtw);
    cudaGetSymbolAddress((void**)&deltah, h_delta);
    cudaGetSymbolAddress((void**)&ygh,    h_yg);
    cudaGetSymbolAddress((void**)&outwh,  h_outw);
    cudaGetSymbolAddress((void**)&houth,  h_hout);
    cudaGetSymbolAddress((void**)&lnouth, h_lnout);
    cudaGetSymbolAddress((void**)&fcwh,   h_fcw);

    cudaFuncSetAttribute((const void*)gemm_h<0,false,true,__half>, cudaFuncAttributeMaxDynamicSharedMemorySize, GSMEM);
    cudaFuncSetAttribute((const void*)gemm_h<1,false,true,__half>, cudaFuncAttributeMaxDynamicSharedMemorySize, GSMEM);
    cudaFuncSetAttribute((const void*)gemm_h<2,false,false,float>, cudaFuncAttributeMaxDynamicSharedMemorySize, GSMEM);
    cudaFuncSetAttribute((const void*)gemm_h<0,true,false,float>,  cudaFuncAttributeMaxDynamicSharedMemorySize, GSMEM);

    // 0) all weight conversions
    {
        const long total = (long)2*DI*DM + 96*DI + DI*DTR + (long)DM*DI + (long)QUES*DM;
        int blocks = (int)((total/4 + 255) / 256);
        f2h_all_kernel<<<blocks, 256>>>(inw, xpw, dtw, outw, fcw,
                                        inwh, xpwh, dtwh, outwh, fcwh);
    }

    // 1) embed + concat + LN0 -> itemh (fp16)
    embed_ln0_kernel<<<BL, 256>>>(x, qid, emb, qc, ln0g, ln0b, itemh);

    // 2) in_proj -> ur fp16 (N=4096, unguarded)
    gemm_h<0,false,true,__half><<<dim3(2*DI/128, BL/128), 256, GSMEM>>>(itemh, DM, inwh, DM, urh, 2*DI,
                                                                        BL, 2*DI, DM, nullptr);

    // 3) depthwise conv + SiLU -> ucv fp16
    conv_silu_kernel<<<dim3(DI/256, LL/CONV_CHUNK, BB), 256>>>(urh, convw, convb, ucvh);

    // 4) x_proj split-K=4 -> dbl fp32, then fp16 copy
    zero_kernel<<<(BL*96 + 1023)/1024, 1024>>>(dbl, BL*96);
    gemm_h<0,true,false,float><<<dim3(1, BL/128, 4), 256, GSMEM>>>(ucvh, DI, xpwh, DI, dbl, 96,
                                                                   BL, 96, DI/4, nullptr);
    f2h_kernel<<<(BL*96/4 + 255)/256, 256>>>(dbl, dblh, BL*96);

    // 5) dt_proj + softplus -> delta fp16 (N=2048, unguarded)
    gemm_h<1,false,true,__half><<<dim3(DI/128, BL/128), 256, GSMEM>>>(dblh, 96, dtwh, DTR, deltah, DI,
                                                                      BL, DI, DTR, dtb);

    // 6) selective scan + gate -> yg fp16
    scan_kernel<<<dim3(DI/16, BB), 256>>>(deltah, ucvh, dbl, urh, alog, dpar, ygh);

    // 7) out_proj -> hout fp16 (N=1024, unguarded)
    gemm_h<0,false,true,__half><<<dim3(DM/128, BL/128), 256, GSMEM>>>(ygh, DI, outwh, DI, houth, DM,
                                                                      BL, DM, DI, nullptr);

    // 8) residual + LN1 (fp16 inputs) -> lnout fp16
    add_ln_kernel<<<BL, 256>>>(houth, itemh, ln1g, ln1b, lnouth);

    // 9) fc + bias + sigmoid(fast) -> out fp32 (N=4000, guarded)
    gemm_h<2,false,false,float><<<dim3((QUES+127)/128, BL/128), 256, GSMEM>>>(lnouth, DM, fcwh, DM, out, QUES,
                                                                              BL, QUES, DM, fcb);
}

// round 16
// speedup vs baseline: 1.0087x; 1.0087x over previous
#include <cuda_runtime.h>
#include <cuda_fp16.h>
#include <cstdint>
#include <math.h>

// ---------------------------------------------------------------------------
// Problem constants
// ---------------------------------------------------------------------------
#define BB   8
#define LL   1024
#define BL   (BB*LL)
#define QUES 4000
#define EMB  256
#define DM   1024
#define DI   2048
#define NN   16
#define DTR  64

// ---------------------------------------------------------------------------
// Scratch (static device allocations)
// ---------------------------------------------------------------------------
__device__ float  g_dbl  [BL*96];

__device__ __half h_item [BL*DM];
__device__ __half h_inw  [2*DI*DM];
__device__ __half h_ur   [(size_t)BL*2*DI];
__device__ __half h_ucv  [(size_t)BL*DI];
__device__ __half h_xpw  [96*DI];
__device__ __half h_dbl  [BL*96];
__device__ __half h_dtw  [DI*DTR];
__device__ __half h_delta[(size_t)BL*DI];
__device__ __half h_yg   [(size_t)BL*DI];
__device__ __half h_outw [DM*DI];
__device__ __half h_hout [BL*DM];
__device__ __half h_lnout[BL*DM];
__device__ __half h_fcw  [QUES*DM];

// ---------------------------------------------------------------------------
// PTX helpers (arch-generic, sm_80-era)
// ---------------------------------------------------------------------------
__device__ __forceinline__ uint32_t smem_u32(const void* p) {
    uint32_t a;
    asm("{ .reg .u64 t; cvta.to.shared.u64 t, %1; cvt.u32.u64 %0, t; }" : "=r"(a) : "l"(p));
    return a;
}
__device__ __forceinline__ void cp_async16(uint32_t dst, const void* src, int src_bytes) {
    asm volatile("cp.async.cg.shared.global [%0], [%1], 16, %2;"
                 :: "r"(dst), "l"(src), "r"(src_bytes) : "memory");
}
__device__ __forceinline__ void cp_async16u(uint32_t dst, const void* src) {
    asm volatile("cp.async.cg.shared.global [%0], [%1], 16;"
                 :: "r"(dst), "l"(src) : "memory");
}
#define CP_COMMIT()  asm volatile("cp.async.commit_group;" ::: "memory")
#define CP_WAIT(n)   asm volatile("cp.async.wait_group %0;" :: "n"(n) : "memory")

__device__ __forceinline__ void ldsm_x4(uint32_t& r0, uint32_t& r1, uint32_t& r2, uint32_t& r3,
                                        uint32_t addr) {
    asm volatile("ldmatrix.sync.aligned.m8n8.x4.shared.b16 {%0,%1,%2,%3}, [%4];"
                 : "=r"(r0), "=r"(r1), "=r"(r2), "=r"(r3) : "r"(addr));
}
__device__ __forceinline__ void mma_f16(float& c0, float& c1, float& c2, float& c3,
                                        uint32_t a0, uint32_t a1, uint32_t a2, uint32_t a3,
                                        uint32_t b0, uint32_t b1) {
    asm volatile(
        "mma.sync.aligned.m16n8k16.row.col.f32.f16.f16.f32 "
        "{%0,%1,%2,%3}, {%4,%5,%6,%7}, {%8,%9}, {%0,%1,%2,%3};"
        : "+f"(c0), "+f"(c1), "+f"(c2), "+f"(c3)
        : "r"(a0), "r"(a1), "r"(a2), "r"(a3), "r"(b0), "r"(b1));
}

// ---------------------------------------------------------------------------
// fp16 GEMM: C[M,N](OutT) = A[M,K](half,lda) * B[N,K](half,ldb)^T
// CTA 128x128, BK=32, 8 warps (64x32 warp tiles), 5-stage cp.async.
// NB=true: N%128==0 guaranteed (no B bounds checks).
// EPI: 0 none, 1 bias+softplus(fast), 2 bias+sigmoid(fast)
// ---------------------------------------------------------------------------
#define ROWB   80
#define ATILE_B (128*ROWB)
#define STAGE_B (2*ATILE_B)
#define NSTAGES 5
#define GSMEM   (NSTAGES*STAGE_B)       // 102400 B

template<int EPI, bool SPLITK, bool NB, typename OutT>
__global__ __launch_bounds__(256, 2)
void gemm_h(const __half* __restrict__ A, int lda,
            const __half* __restrict__ B, int ldb,
            OutT* __restrict__ C, int ldc,
            int M, int N, int K, const float* __restrict__ bias)
{
    extern __shared__ char sm[];
    const uint32_t sbase = smem_u32(sm);
    const int tid  = threadIdx.x;
    const int lane = tid & 31;
    const int wid  = tid >> 5;

    const int m0 = blockIdx.y * 128;
    const int n0 = blockIdx.x * 128;
    const int kbase = SPLITK ? blockIdx.z * K : 0;
    const int warp_m = (wid >> 2) * 64;
    const int warp_n = (wid & 3) * 32;

    float acc[4][4][4];
    #pragma unroll
    for (int mi = 0; mi < 4; mi++)
        #pragma unroll
        for (int ni = 0; ni < 4; ni++)
            #pragma unroll
            for (int r = 0; r < 4; r++) acc[mi][ni][r] = 0.f;

    const int NC = K >> 5;

    auto load_stage = [&](int ch, int st) {
        const int k0 = kbase + (ch << 5);
        uint32_t aB = sbase + (uint32_t)st * STAGE_B;
        uint32_t bB = aB + ATILE_B;
        #pragma unroll
        for (int it = 0; it < 2; it++) {
            int idx = tid + it * 256;
            int row = idx >> 2, c = idx & 3;
            cp_async16u(aB + row * ROWB + c * 16,
                        A + (size_t)(m0 + row) * lda + k0 + c * 8);
        }
        #pragma unroll
        for (int it = 0; it < 2; it++) {
            int idx = tid + it * 256;
            int row = idx >> 2, c = idx & 3;
            int gn = n0 + row;
            if constexpr (NB) {
                cp_async16u(bB + row * ROWB + c * 16,
                            B + (size_t)gn * ldb + k0 + c * 8);
            } else {
                int ok = (gn < N) ? 16 : 0;
                const __half* src = B + (size_t)(ok ? gn : 0) * ldb + k0 + c * 8;
                cp_async16(bB + row * ROWB + c * 16, src, ok);
            }
        }
    };

    #pragma unroll
    for (int s = 0; s < 4; s++)
        if (s < NC) { load_stage(s, s); CP_COMMIT(); }

    const uint32_t aOff = (uint32_t)((warp_m + (lane & 15)) * ROWB + ((lane >> 4) << 3) * 2);
    const uint32_t bOff = (uint32_t)(ATILE_B
                        + (warp_n + (lane & 7) + ((lane >> 4) << 3)) * ROWB
                        + (((lane >> 3) & 1) << 3) * 2);

    int stage = 0;
    for (int ch = 0; ch < NC; ch++) {
        const int rem = NC - ch - 1;
        if (rem >= 3)      CP_WAIT(3);
        else if (rem == 2) CP_WAIT(2);
        else if (rem == 1) CP_WAIT(1);
        else               CP_WAIT(0);
        __syncthreads();
        if (ch + 4 < NC) {
            int st = stage + 4; if (st >= NSTAGES) st -= NSTAGES;
            load_stage(ch + 4, st);
            CP_COMMIT();
        }

        const uint32_t stg = sbase + (uint32_t)stage * STAGE_B;
        stage++; if (stage == NSTAGES) stage = 0;

        uint32_t a[2][4][4], b[2][2][4];
        #pragma unroll
        for (int ks = 0; ks < 2; ks++) {
            const uint32_t kb = (uint32_t)(ks * 32);
            #pragma unroll
            for (int mi = 0; mi < 4; mi++)
                ldsm_x4(a[ks][mi][0], a[ks][mi][1], a[ks][mi][2], a[ks][mi][3],
                        stg + aOff + (uint32_t)(mi * 16 * ROWB) + kb);
            #pragma unroll
            for (int p = 0; p < 2; p++)
                ldsm_x4(b[ks][p][0], b[ks][p][1], b[ks][p][2], b[ks][p][3],
                        stg + bOff + (uint32_t)(p * 16 * ROWB) + kb);
        }
        #pragma unroll
        for (int ks = 0; ks < 2; ks++)
            #pragma unroll
            for (int mi = 0; mi < 4; mi++)
                #pragma unroll
                for (int ni = 0; ni < 4; ni++) {
                    const int p = ni >> 1, sel = (ni & 1) * 2;
                    mma_f16(acc[mi][ni][0], acc[mi][ni][1], acc[mi][ni][2], acc[mi][ni][3],
                            a[ks][mi][0], a[ks][mi][1], a[ks][mi][2], a[ks][mi][3],
                            b[ks][p][sel], b[ks][p][sel + 1]);
                }
    }

    const int g  = lane >> 2;
    const int tg = lane & 3;
    #pragma unroll
    for (int mi = 0; mi < 4; mi++) {
        #pragma unroll
        for (int ni = 0; ni < 4; ni++) {
            int row = m0 + warp_m + mi * 16 + g;
            int col = n0 + warp_n + ni * 8 + 2 * tg;
            float v[4] = {acc[mi][ni][0], acc[mi][ni][1], acc[mi][ni][2], acc[mi][ni][3]};
            if constexpr (SPLITK) {
                float* Cf = (float*)C;
                if (col < N) {
                    atomicAdd(Cf + (size_t)row * ldc + col,       v[0]);
                    atomicAdd(Cf + (size_t)(row + 8) * ldc + col, v[2]);
                }
                if (col + 1 < N) {
                    atomicAdd(Cf + (size_t)row * ldc + col + 1,       v[1]);
                    atomicAdd(Cf + (size_t)(row + 8) * ldc + col + 1, v[3]);
                }
                continue;
            }
            if (EPI != 0) {
                #pragma unroll
                for (int j = 0; j < 4; j++) {
                    int cc = col + (j & 1);
                    if (NB || cc < N) {
                        float t = v[j] + bias[cc];
                        if (EPI == 1) v[j] = (t > 20.f) ? t : __logf(1.f + __expf(t));
                        else          v[j] = __fdividef(1.f, 1.f + __expf(-t));
                    }
                }
            }
            if (NB || col + 1 < N) {
                if constexpr (sizeof(OutT) == 2) {
                    *(__half2*)((__half*)C + (size_t)row * ldc + col)
                        = __floats2half2_rn(v[0], v[1]);
                    *(__half2*)((__half*)C + (size_t)(row + 8) * ldc + col)
                        = __floats2half2_rn(v[2], v[3]);
                } else {
                    *(float2*)((float*)C + (size_t)row * ldc + col)       = make_float2(v[0], v[1]);
                    *(float2*)((float*)C + (size_t)(row + 8) * ldc + col) = make_float2(v[2], v[3]);
                }
            } else if (col < N) {
                if constexpr (sizeof(OutT) == 2) {
                    ((__half*)C)[(size_t)row * ldc + col]       = __float2half(v[0]);
                    ((__half*)C)[(size_t)(row + 8) * ldc + col] = __float2half(v[2]);
                } else {
                    ((float*)C)[(size_t)row * ldc + col]       = v[0];
                    ((float*)C)[(size_t)(row + 8) * ldc + col] = v[2];
                }
            }
        }
    }
}

// ---------------------------------------------------------------------------
// Fused weight conversion
// ---------------------------------------------------------------------------
__global__ void f2h_all_kernel(const float* w0, const float* w1, const float* w2,
                               const float* w3, const float* w4,
                               __half* d0, __half* d1, __half* d2,
                               __half* d3, __half* d4)
{
    const int n0 = 2*DI*DM, n1 = 96*DI, n2 = DI*DTR, n3 = DM*DI, n4 = QUES*DM;
    long i = ((long)blockIdx.x * 256 + threadIdx.x) * 4;
    const float* src; __half* dst; long j = i;
    if      (j < n0)         { src = w0; dst = d0; }
    else if ((j -= n0) < n1) { src = w1; dst = d1; }
    else if ((j -= n1) < n2) { src = w2; dst = d2; }
    else if ((j -= n2) < n3) { src = w3; dst = d3; }
    else if ((j -= n3) < n4) { src = w4; dst = d4; }
    else return;
    float4 v = *(const float4*)(src + j);
    __half2* d = (__half2*)(dst + j);
    d[0] = __floats2half2_rn(v.x, v.y);
    d[1] = __floats2half2_rn(v.z, v.w);
}

__global__ void f2h_kernel(const float* __restrict__ src, __half* __restrict__ dst, int n) {
    int i = (blockIdx.x * 256 + threadIdx.x) * 4;
    if (i < n) {
        float4 v = *(const float4*)(src + i);
        __half2* d = (__half2*)(dst + i);
        d[0] = __floats2half2_rn(v.x, v.y);
        d[1] = __floats2half2_rn(v.z, v.w);
    }
}

__global__ void zero_kernel(float* __restrict__ p, int n) {
    int i = blockIdx.x * 1024 + threadIdx.x;
    if (i < n) p[i] = 0.f;
}

// ---------------------------------------------------------------------------
// Embedding gather + concat + LayerNorm0 -> fp16
// ---------------------------------------------------------------------------
__global__ void embed_ln0_kernel(const int* __restrict__ x, const int* __restrict__ qid,
                                 const float* __restrict__ emb, const float* __restrict__ qc,
                                 const float* __restrict__ g, const float* __restrict__ b,
                                 __half* __restrict__ itemh)
{
    int tok = blockIdx.x;
    int t   = threadIdx.x;
    int xv  = x[tok];
    int qv  = qid[tok];

    float v[4];
    v[0] = emb[(size_t)xv*EMB + t];
    v[1] = qc [(size_t)qv*768 + t];
    v[2] = qc [(size_t)qv*768 + 256 + t];
    v[3] = qc [(size_t)qv*768 + 512 + t];

    float s  = v[0]+v[1]+v[2]+v[3];
    float sq = v[0]*v[0]+v[1]*v[1]+v[2]*v[2]+v[3]*v[3];
    #pragma unroll
    for (int o = 16; o > 0; o >>= 1) {
        s  += __shfl_xor_sync(0xffffffffu, s,  o);
        sq += __shfl_xor_sync(0xffffffffu, sq, o);
    }
    __shared__ float ws[8], wq[8];
    int lane = t & 31, warp = t >> 5;
    if (lane == 0) { ws[warp] = s; wq[warp] = sq; }
    __syncthreads();
    __shared__ float s_mean, s_rstd;
    if (t == 0) {
        float ts = 0.f, tq = 0.f;
        #pragma unroll
        for (int i = 0; i < 8; i++) { ts += ws[i]; tq += wq[i]; }
        float mean = ts * (1.0f/DM);
        float var  = tq * (1.0f/DM) - mean*mean;
        s_mean = mean;
        s_rstd = rsqrtf(var + 1e-12f);
    }
    __syncthreads();
    float mean = s_mean, rstd = s_rstd;
    #pragma unroll
    for (int i = 0; i < 4; i++) {
        int j = t + i*256;
        itemh[(size_t)tok*DM + j] = __float2half((v[i] - mean) * rstd * g[j] + b[j]);
    }
}

// ---------------------------------------------------------------------------
// Residual add (fp16 + fp16) + LayerNorm1 -> fp16
// ---------------------------------------------------------------------------
__global__ void add_ln_kernel(const __half* __restrict__ a, const __half* __restrict__ res,
                              const float* __restrict__ g, const float* __restrict__ b,
                              __half* __restrict__ out)
{
    int tok = blockIdx.x;
    int t   = threadIdx.x;
    float v[4];
    #pragma unroll
    for (int i = 0; i < 4; i++) {
        int j = t + i*256;
        v[i] = __half2float(a[(size_t)tok*DM + j]) + __half2float(res[(size_t)tok*DM + j]);
    }
    float s  = v[0]+v[1]+v[2]+v[3];
    float sq = v[0]*v[0]+v[1]*v[1]+v[2]*v[2]+v[3]*v[3];
    #pragma unroll
    for (int o = 16; o > 0; o >>= 1) {
        s  += __shfl_xor_sync(0xffffffffu, s,  o);
        sq += __shfl_xor_sync(0xffffffffu, sq, o);
    }
    __shared__ float ws[8], wq[8];
    int lane = t & 31, warp = t >> 5;
    if (lane == 0) { ws[warp] = s; wq[warp] = sq; }
    __syncthreads();
    __shared__ float s_mean, s_rstd;
    if (t == 0) {
        float ts = 0.f, tq = 0.f;
        #pragma unroll
        for (int i = 0; i < 8; i++) { ts += ws[i]; tq += wq[i]; }
        float mean = ts * (1.0f/DM);
        float var  = tq * (1.0f/DM) - mean*mean;
        s_mean = mean;
        s_rstd = rsqrtf(var + 1e-12f);
    }
    __syncthreads();
    float mean = s_mean, rstd = s_rstd;
    #pragma unroll
    for (int i = 0; i < 4; i++) {
        int j = t + i*256;
        out[(size_t)tok*DM + j] = __float2half((v[i] - mean) * rstd * g[j] + b[j]);
    }
}

// ---------------------------------------------------------------------------
// Depthwise causal conv (K=4) + SiLU — 64-long l-chunks (measured champion)
// ---------------------------------------------------------------------------
#define CONV_CHUNK 64
__global__ void conv_silu_kernel(const __half* __restrict__ ur,
                                 const float* __restrict__ w,
                                 const float* __restrict__ cb,
                                 __half* __restrict__ outh)
{
    int d  = blockIdx.x * 256 + threadIdx.x;
    int l0 = blockIdx.y * CONV_CHUNK;
    int b  = blockIdx.z;
    float w0 = w[d*4+0], w1 = w[d*4+1], w2 = w[d*4+2], w3 = w[d*4+3];
    float bias = cb[d];
    size_t rbase = (size_t)b * LL;

    float x0 = 0.f, x1 = 0.f, x2 = 0.f;
    if (l0 >= 1) x2 = __half2float(ur[(rbase + l0 - 1)*(2*DI) + d]);
    if (l0 >= 2) x1 = __half2float(ur[(rbase + l0 - 2)*(2*DI) + d]);
    if (l0 >= 3) x0 = __half2float(ur[(rbase + l0 - 3)*(2*DI) + d]);

    #pragma unroll 4
    for (int l = l0; l < l0 + CONV_CHUNK; l++) {
        size_t idx = rbase + l;
        float xc = __half2float(ur[idx*(2*DI) + d]);
        float c  = fmaf(x0, w0, fmaf(x1, w1, fmaf(x2, w2, fmaf(xc, w3, bias))));
        float o  = c * __fdividef(1.f, 1.f + __expf(-c));
        outh[idx*DI + d] = __float2half(o);
        x0 = x1; x1 = x2; x2 = xc;
    }
}

// ---------------------------------------------------------------------------
// Selective scan v2: smem-staged, cp.async double-buffered, coalesced.
// ---------------------------------------------------------------------------
#define SCH 32
__global__ __launch_bounds__(256)
void scan_kernel(const __half* __restrict__ delta,
                 const __half* __restrict__ ucv,
                 const float*  __restrict__ dbl,
                 const __half* __restrict__ ur,
                 const float*  __restrict__ A_log,
                 const float*  __restrict__ D_param,
                 __half* __restrict__ yg)
{
    __shared__ __align__(16) __half sdelta[2][SCH][16];
    __shared__ __align__(16) __half sucv  [2][SCH][16];
    __shared__ __align__(16) __half sr    [2][SCH][16];
    __shared__ __align__(16) float  sdbl  [2][SCH][32];
    __shared__ __align__(16) __half sy    [SCH][16];

    const int t  = threadIdx.x;
    const int n  = t & 15;
    const int dd = t >> 4;
    const int d0 = blockIdx.x * 16;
    const int b  = blockIdx.y;
    const int d  = d0 + dd;
    const size_t base = (size_t)b * LL;

    const float A  = -expf(A_log[d*NN + n]);
    const float Dd = D_param[d];
    float h = 0.f;

    auto load_chunk = [&](int c, int buf) {
        const size_t l0 = base + (size_t)c * SCH;
        if (t < 64) {
            int l = t >> 1, p = t & 1;
            cp_async16u(smem_u32(&sdelta[buf][l][p*8]),
                        delta + (l0 + l)*DI + d0 + p*8);
        } else if (t < 128) {
            int tt = t - 64; int l = tt >> 1, p = tt & 1;
            cp_async16u(smem_u32(&sucv[buf][l][p*8]),
                        ucv + (l0 + l)*DI + d0 + p*8);
        } else if (t < 192) {
            int tt = t - 128; int l = tt >> 1, p = tt & 1;
            cp_async16u(smem_u32(&sr[buf][l][p*8]),
                        ur + (l0 + l)*(size_t)(2*DI) + DI + d0 + p*8);
        }
        {
            int l = t >> 3, p = t & 7;
            cp_async16u(smem_u32(&sdbl[buf][l][p*4]),
                        dbl + (l0 + l)*96 + 64 + p*4);
        }
    };

    load_chunk(0, 0);
    CP_COMMIT();

    const int NCH = LL / SCH;
    for (int c = 0; c < NCH; c++) {
        const int buf = c & 1;
        if (c + 1 < NCH) { load_chunk(c + 1, (c + 1) & 1); CP_COMMIT(); CP_WAIT(1); }
        else             { CP_WAIT(0); }
        __syncthreads();

        #pragma unroll 4
        for (int l = 0; l < SCH; l++) {
            float dlt = __half2float(sdelta[buf][l][dd]);
            float uu  = __half2float(sucv  [buf][l][dd]);
            float Bv  = sdbl[buf][l][n];
            float Cv  = sdbl[buf][l][16 + n];
            h = fmaf(__expf(dlt * A), h, dlt * uu * Bv);
            float p = h * Cv;
            p += __shfl_xor_sync(0xffffffffu, p, 8);
            p += __shfl_xor_sync(0xffffffffu, p, 4);
            p += __shfl_xor_sync(0xffffffffu, p, 2);
            p += __shfl_xor_sync(0xffffffffu, p, 1);
            if (n == 0) {
                float r  = __half2float(sr[buf][l][dd]);
                float g_ = r * __fdividef(1.f, 1.f + __expf(-r));
                sy[l][dd] = __float2half((p + uu * Dd) * g_);
            }
        }
        __syncthreads();
        {
            int l = t >> 3, p = t & 7;
            *(__half2*)(yg + (base + (size_t)c * SCH + l)*DI + d0 + p*2)
                = *(__half2*)&sy[l][p*2];
        }
    }
}

// ---------------------------------------------------------------------------
// Launch
// ---------------------------------------------------------------------------
extern "C" void kernel_launch(void* const* d_in, const int* in_sizes, int n_in,
                              void* d_out, int out_size)
{
    const int*   x     = (const int*)  d_in[0];
    const int*   qid   = (const int*)  d_in[1];
    const float* emb   = (const float*)d_in[2];
    const float* qc    = (const float*)d_in[3];
    const float* ln0g  = (const float*)d_in[4];
    const float* ln0b  = (const float*)d_in[5];
    const float* inw   = (const float*)d_in[6];
    const float* convw = (const float*)d_in[7];
    const float* convb = (const float*)d_in[8];
    const float* xpw   = (const float*)d_in[9];
    const float* dtw   = (const float*)d_in[10];
    const float* dtb   = (const float*)d_in[11];
    const float* alog  = (const float*)d_in[12];
    const float* dpar  = (const float*)d_in[13];
    const float* outw  = (const float*)d_in[14];
    const float* ln1g  = (const float*)d_in[15];
    const float* ln1b  = (const float*)d_in[16];
    const float* fcw   = (const float*)d_in[17];
    const float* fcb   = (const float*)d_in[18];
    float* out = (float*)d_out;

    float *dbl;
    cudaGetSymbolAddress((void**)&dbl, g_dbl);

    __half *itemh, *inwh, *urh, *ucvh, *xpwh, *dblh, *dtwh, *deltah, *ygh, *outwh, *houth, *lnouth, *fcwh;
    cudaGetSymbolAddress((void**)&itemh,  h_item);
    cudaGetSymbolAddress((void**)&inwh,   h_inw);
    cudaGetSymbolAddress((void**)&urh,    h_ur);
    cudaGetSymbolAddress((void**)&ucvh,   h_ucv);
    cudaGetSymbolAddress((void**)&xpwh,   h_xpw);
    cudaGetSymbolAddress((void**)&dblh,   h_dbl);
    cudaGetSymbolAddress((void**)&dtwh,   h_dtw);
    cudaGetSymbolAddress((void**)&deltah, h_delta);
    cudaGetSymbolAddress((void**)&ygh,    h_yg);
    cudaGetSymbolAddress((void**)&outwh,  h_outw);
    cudaGetSymbolAddress((void**)&houth,  h_hout);
    cudaGetSymbolAddress((void**)&lnouth, h_lnout);
    cudaGetSymbolAddress((void**)&fcwh,   h_fcw);

    cudaFuncSetAttribute((const void*)gemm_h<0,false,true,__half>, cudaFuncAttributeMaxDynamicSharedMemorySize, GSMEM);
    cudaFuncSetAttribute((const void*)gemm_h<1,false,true,__half>, cudaFuncAttributeMaxDynamicSharedMemorySize, GSMEM);
    cudaFuncSetAttribute((const void*)gemm_h<2,false,false,float>, cudaFuncAttributeMaxDynamicSharedMemorySize, GSMEM);
    cudaFuncSetAttribute((const void*)gemm_h<0,true,false,float>,  cudaFuncAttributeMaxDynamicSharedMemorySize, GSMEM);

    // 0) all weight conversions
    {
        const long total = (long)2*DI*DM + 96*DI + DI*DTR + (long)DM*DI + (long)QUES*DM;
        int blocks = (int)((total/4 + 255) / 256);
        f2h_all_kernel<<<blocks, 256>>>(inw, xpw, dtw, outw, fcw,
                                        inwh, xpwh, dtwh, outwh, fcwh);
    }

    // 1) embed + concat + LN0 -> itemh (fp16)
    embed_ln0_kernel<<<BL, 256>>>(x, qid, emb, qc, ln0g, ln0b, itemh);

    // 2) in_proj -> ur fp16 (N=4096, unguarded)
    gemm_h<0,false,true,__half><<<dim3(2*DI/128, BL/128), 256, GSMEM>>>(itemh, DM, inwh, DM, urh, 2*DI,
                                                                        BL, 2*DI, DM, nullptr);

    // 3) depthwise conv + SiLU -> ucv fp16
    conv_silu_kernel<<<dim3(DI/256, LL/CONV_CHUNK, BB), 256>>>(urh, convw, convb, ucvh);

    // 4) x_proj split-K=4 -> dbl fp32, then fp16 copy
    zero_kernel<<<(BL*96 + 1023)/1024, 1024>>>(dbl, BL*96);
    gemm_h<0,true,false,float><<<dim3(1, BL/128, 4), 256, GSMEM>>>(ucvh, DI, xpwh, DI, dbl, 96,
                                                                   BL, 96, DI/4, nullptr);
    f2h_kernel<<<(BL*96/4 + 255)/256, 256>>>(dbl, dblh, BL*96);

    // 5) dt_proj + softplus -> delta fp16 (N=2048, unguarded)
    gemm_h<1,false,true,__half><<<dim3(DI/128, BL/128), 256, GSMEM>>>(dblh, 96, dtwh, DTR, deltah, DI,
                                                                      BL, DI, DTR, dtb);

    // 6) selective scan + gate -> yg fp16
    scan_kernel<<<dim3(DI/16, BB), 256>>>(deltah, ucvh, dbl, urh, alog, dpar, ygh);

    // 7) out_proj -> hout fp16 (N=1024, unguarded)
    gemm_h<0,false,true,__half><<<dim3(DM/128, BL/128), 256, GSMEM>>>(ygh, DI, outwh, DI, houth, DM,
                                                                      BL, DM, DI, nullptr);

    // 8) residual + LN1 (fp16 inputs) -> lnout fp16
    add_ln_kernel<<<BL, 256>>>(houth, itemh, ln1g, ln1b, lnouth);

    // 9) fc + bias + sigmoid(fast) -> out fp32 (N=4000, guarded)
    gemm_h<2,false,false,float><<<dim3((QUES+127)/128, BL/128), 256, GSMEM>>>(lnouth, DM, fcwh, DM, out, QUES,
                                                                              BL, QUES, DM, fcb);
}